// round 6
// baseline (speedup 1.0000x reference)
#include <cuda_runtime.h>
#include <cuda_fp16.h>
#include <cstdint>

// Problem constants
#define Bn   16
#define Tn   512
#define Fn   32
#define CIn  128
#define COn  128
#define Kn   3
#define DILn 2

#define TILE_M   128
#define NCHUNKS  12            // 3 taps * 4 ci-chunks of 32
#define NTHREADS 256           // 8 warps, 32x64 warp tiles
#define NSTAGES  3

// A resident block: 4 ci-planes x 136 rows x 64B (fp16), rows 0..131 used
#define A_PLANE_BYTES (136 * 64)            // 8704
#define A_TOTAL       (4 * A_PLANE_BYTES)   // 34816
// B stage: 128 o-rows x 32 ci fp16 = 64B rows -> 8KB
#define B_STAGE_BYTES 8192
#define DYN_SMEM (A_TOTAL + NSTAGES * B_STAGE_BYTES + 1024)

#define SWZ64(off) ((off) ^ (((off) >> 3) & 0x30))

// Weights as fp16: wBh[f][tap][o][ci]
__device__ __half g_wBh[Fn * Kn * COn * CIn];

// ---------------------------------------------------------------------------
__global__ void prep_w(const float* __restrict__ w) {
    int idx = blockIdx.x * blockDim.x + threadIdx.x;
    const int total = Fn * Kn * COn * CIn;
    if (idx >= total) return;
    int i = idx % CIn;
    int o = (idx / CIn) % COn;
    int k = (idx / (CIn * COn)) % Kn;
    int f = idx / (CIn * COn * Kn);
    g_wBh[idx] = __float2half_rn(w[((f * COn + o) * CIn + i) * Kn + k]);
}

// ---------------------------------------------------------------------------
__device__ __forceinline__ uint32_t smem_u32(const void* p) {
    uint32_t a;
    asm("{ .reg .u64 t; cvta.to.shared.u64 t, %1; cvt.u32.u64 %0, t; }" : "=r"(a) : "l"(p));
    return a;
}
__device__ __forceinline__ void cp16(uint32_t saddr, const void* gaddr) {
    asm volatile("cp.async.cg.shared.global [%0], [%1], 16;"
                 :: "r"(saddr), "l"(gaddr));
}
__device__ __forceinline__ void sts64(uint32_t saddr, uint32_t v0, uint32_t v1) {
    asm volatile("st.shared.v2.b32 [%0], {%1, %2};" :: "r"(saddr), "r"(v0), "r"(v1));
}
__device__ __forceinline__ void ldsm_x4(uint32_t& r0, uint32_t& r1, uint32_t& r2, uint32_t& r3,
                                        uint32_t addr) {
    asm volatile("ldmatrix.sync.aligned.m8n8.x4.shared.b16 {%0,%1,%2,%3}, [%4];"
                 : "=r"(r0), "=r"(r1), "=r"(r2), "=r"(r3) : "r"(addr));
}
__device__ __forceinline__ void mma_f16(float* c, const uint32_t* a, const uint32_t* b) {
    asm volatile(
        "mma.sync.aligned.m16n8k16.row.col.f32.f16.f16.f32 "
        "{%0,%1,%2,%3}, {%4,%5,%6,%7}, {%8,%9}, {%0,%1,%2,%3};"
        : "+f"(c[0]), "+f"(c[1]), "+f"(c[2]), "+f"(c[3])
        : "r"(a[0]), "r"(a[1]), "r"(a[2]), "r"(a[3]), "r"(b[0]), "r"(b[1]));
}

// ---------------------------------------------------------------------------
// CTA = 128 t-rows x 128 CO for one (b, f). 8 warps, warp tile 32x64.
// A (x) converted fp32->fp16 once into resident smem; B streamed (fp16).
// ---------------------------------------------------------------------------
__global__ __launch_bounds__(NTHREADS, 2)
void conv_mma_kernel(const float* __restrict__ x,
                     const float* __restrict__ bias,
                     float* __restrict__ y) {
    extern __shared__ char dsm[];
    __shared__ float s_bias[COn];

    const int t0 = blockIdx.x * TILE_M;
    const int f  = blockIdx.y;
    const int b  = blockIdx.z;
    const int tid = threadIdx.x;
    const int wid = tid >> 5;
    const int lane = tid & 31;
    const int wm = (wid >> 1) * 32;      // warp M base (0,32,64,96)
    const int wn = (wid & 1) * 64;       // warp N base (0,64)

    const uint32_t smb = (smem_u32(dsm) + 1023u) & ~1023u;
    const uint32_t Abase = smb;                       // A planes
    const uint32_t Bbase = smb + A_TOTAL;             // B stages

    const float* xb = x + ((long long)b * Tn * Fn + f) * CIn;   // + t*4096 + ci
    const __half* wf = g_wBh + (long long)f * Kn * COn * CIn;   // + tap*16384 + o*128 + ci

    if (tid < COn) s_bias[tid] = bias[f * COn + tid];

    // ---- B loader: chunk c -> stage s (2x cp16 per thread) ----
    const int b_lrow = tid >> 1;             // o row 0..127
    const int b_lcb  = (tid & 1) * 2;        // 16B col base (0 or 2)
    auto load_B = [&](int c, int s) {
        const int ktap = c >> 2;
        const int ci0  = (c & 3) * 32;
        const __half* gb = wf + (long long)ktap * (COn * CIn) + (long long)b_lrow * CIn + ci0;
        const uint32_t Bb = Bbase + s * B_STAGE_BYTES;
        #pragma unroll
        for (int j = 0; j < 2; j++) {
            uint32_t off = b_lrow * 64 + (b_lcb + j) * 16;
            cp16(Bb + SWZ64(off), gb + (b_lcb + j) * 8);
        }
    };

    // ---- prologue: kick off B chunks 0,1 ----
    load_B(0, 0);
    asm volatile("cp.async.commit_group;");
    load_B(1, 1);
    asm volatile("cp.async.commit_group;");

    // ---- convert A: x rows t0-4 .. t0+127 (132 rows x 128 ci) -> fp16 planes ----
    // idx -> (row, q): row = idx>>5 (0..131), q = idx&31 (float4 index, ci = 4q)
    for (int idx = tid; idx < 132 * 32; idx += NTHREADS) {
        const int row = idx >> 5;
        const int q   = idx & 31;
        const int tg  = t0 - 4 + row;
        float4 v = make_float4(0.f, 0.f, 0.f, 0.f);
        if (tg >= 0)
            v = *reinterpret_cast<const float4*>(xb + (long long)tg * (Fn * CIn) + q * 4);
        __half2 h0 = __floats2half2_rn(v.x, v.y);
        __half2 h1 = __floats2half2_rn(v.z, v.w);
        const int plane = q >> 3;
        const uint32_t off = row * 64 + (q & 7) * 8;
        sts64(Abase + plane * A_PLANE_BYTES + SWZ64(off),
              *reinterpret_cast<uint32_t*>(&h0), *reinterpret_cast<uint32_t*>(&h1));
    }

    __syncthreads();   // A planes + s_bias ready

    // ---- accumulators (init with bias) ----
    float acc[2][8][4];
    #pragma unroll
    for (int nf = 0; nf < 8; nf++) {
        const int n = wn + nf * 8 + (lane & 3) * 2;
        const float b0 = s_bias[n], b1 = s_bias[n + 1];
        #pragma unroll
        for (int mf = 0; mf < 2; mf++) {
            acc[mf][nf][0] = b0; acc[mf][nf][1] = b1;
            acc[mf][nf][2] = b0; acc[mf][nf][3] = b1;
        }
    }

    // ldmatrix lane addressing (16B units within 64B rows)
    const int a_row = wm + (lane & 15);
    const int a_cb  = (lane >> 4) * 16;                  // k half within kstep
    const int b_row = wn + (lane & 7) + ((lane >> 4) << 3);
    const int b_cb  = ((lane >> 3) & 1) * 16;

    // ---- main loop ----
    #pragma unroll 1
    for (int c = 0; c < NCHUNKS; c++) {
        const int s = c % NSTAGES;
        const int ktap = c >> 2;
        const int plane = c & 3;
        asm volatile("cp.async.wait_group 1;");
        __syncthreads();

        if (c + 2 < NCHUNKS) load_B(c + 2, (c + 2) % NSTAGES);
        asm volatile("cp.async.commit_group;");

        const uint32_t Ab = Abase + plane * A_PLANE_BYTES;
        const uint32_t Bb = Bbase + s * B_STAGE_BYTES;
        const int arow_sh = 2 * ktap;    // tap time-shift in resident rows

        #pragma unroll
        for (int ks = 0; ks < 2; ks++) {
            uint32_t afr[2][4], bfr[8][2];
            #pragma unroll
            for (int mf = 0; mf < 2; mf++)
                ldsm_x4(afr[mf][0], afr[mf][1], afr[mf][2], afr[mf][3],
                        Ab + SWZ64((a_row + mf * 16 + arow_sh) * 64 + ks * 32 + a_cb));
            #pragma unroll
            for (int nf2 = 0; nf2 < 4; nf2++) {
                uint32_t r0, r1, r2, r3;
                ldsm_x4(r0, r1, r2, r3,
                        Bb + SWZ64((b_row + nf2 * 16) * 64 + ks * 32 + b_cb));
                bfr[nf2 * 2][0] = r0;     bfr[nf2 * 2][1] = r1;
                bfr[nf2 * 2 + 1][0] = r2; bfr[nf2 * 2 + 1][1] = r3;
            }
            #pragma unroll
            for (int mf = 0; mf < 2; mf++)
                #pragma unroll
                for (int nf = 0; nf < 8; nf++)
                    mma_f16(acc[mf][nf], afr[mf], bfr[nf]);
        }
    }

    // ---- epilogue ----
    #pragma unroll
    for (int mf = 0; mf < 2; mf++) {
        #pragma unroll
        for (int r2 = 0; r2 < 2; r2++) {
            const int t = t0 + wm + mf * 16 + (lane >> 2) + r2 * 8;
            float* yrow = y + ((long long)(b * Tn + t) * Fn + f) * COn;
            #pragma unroll
            for (int nf = 0; nf < 8; nf++) {
                const int n = wn + nf * 8 + (lane & 3) * 2;
                float2 v = make_float2(acc[mf][nf][r2 * 2], acc[mf][nf][r2 * 2 + 1]);
                *reinterpret_cast<float2*>(yrow + n) = v;
            }
        }
    }
}

// ---------------------------------------------------------------------------
extern "C" void kernel_launch(void* const* d_in, const int* in_sizes, int n_in,
                              void* d_out, int out_size) {
    const float* x    = (const float*)d_in[0];  // [B, T, F, CI]
    const float* w    = (const float*)d_in[1];  // [F, CO, CI, K]
    const float* bias = (const float*)d_in[2];  // [F, CO]
    float* y = (float*)d_out;                   // [B, T, F, CO]
    (void)in_sizes; (void)n_in; (void)out_size;

    {
        const int total = Fn * Kn * COn * CIn;
        prep_w<<<(total + 255) / 256, 256>>>(w);
    }
    {
        static bool attr_set = false;
        if (!attr_set) {
            cudaFuncSetAttribute(conv_mma_kernel,
                                 cudaFuncAttributeMaxDynamicSharedMemorySize, DYN_SMEM);
            attr_set = true;
        }
        dim3 grid(Tn / TILE_M, Fn, Bn);   // (4, 32, 16) = 2048 CTAs
        conv_mma_kernel<<<grid, NTHREADS, DYN_SMEM>>>(x, bias, y);
    }
}

// round 7
// speedup vs baseline: 1.0757x; 1.0757x over previous
#include <cuda_runtime.h>
#include <cuda_fp16.h>
#include <cstdint>

// Problem constants
#define Bn   16
#define Tn   512
#define Fn   32
#define CIn  128
#define COn  128
#define Kn   3
#define DILn 2

#define TILE_M   128
#define NTHREADS 256           // 8 warps, 32x64 warp tiles

// A resident block: 4 ci-planes x 136 rows x 64B (fp16), rows 0..131 used
#define A_PLANE_BYTES (136 * 64)            // 8704
#define A_TOTAL       (4 * A_PLANE_BYTES)   // 34816
// B stage: one full tap = 4 ci-planes x 128 rows x 64B = 32KB; 2 stages
#define B_PLANE_BYTES 8192
#define B_STAGE_BYTES (4 * B_PLANE_BYTES)   // 32768
#define DYN_SMEM (A_TOTAL + 2 * B_STAGE_BYTES)   // 100352

#define SWZ64(off) ((off) ^ (((off) >> 3) & 0x30))

// Weights as fp16: wBh[f][tap][o][ci]
__device__ __half g_wBh[Fn * Kn * COn * CIn];

// ---------------------------------------------------------------------------
__global__ void prep_w(const float* __restrict__ w) {
    int idx = blockIdx.x * blockDim.x + threadIdx.x;
    const int total = Fn * Kn * COn * CIn;
    if (idx >= total) return;
    int i = idx % CIn;
    int o = (idx / CIn) % COn;
    int k = (idx / (CIn * COn)) % Kn;
    int f = idx / (CIn * COn * Kn);
    g_wBh[idx] = __float2half_rn(w[((f * COn + o) * CIn + i) * Kn + k]);
}

// ---------------------------------------------------------------------------
__device__ __forceinline__ uint32_t smem_u32(const void* p) {
    uint32_t a;
    asm("{ .reg .u64 t; cvta.to.shared.u64 t, %1; cvt.u32.u64 %0, t; }" : "=r"(a) : "l"(p));
    return a;
}
__device__ __forceinline__ void cp16(uint32_t saddr, const void* gaddr) {
    asm volatile("cp.async.cg.shared.global [%0], [%1], 16;"
                 :: "r"(saddr), "l"(gaddr));
}
__device__ __forceinline__ void sts64(uint32_t saddr, uint32_t v0, uint32_t v1) {
    asm volatile("st.shared.v2.b32 [%0], {%1, %2};" :: "r"(saddr), "r"(v0), "r"(v1));
}
__device__ __forceinline__ void ldsm_x4(uint32_t& r0, uint32_t& r1, uint32_t& r2, uint32_t& r3,
                                        uint32_t addr) {
    asm volatile("ldmatrix.sync.aligned.m8n8.x4.shared.b16 {%0,%1,%2,%3}, [%4];"
                 : "=r"(r0), "=r"(r1), "=r"(r2), "=r"(r3) : "r"(addr));
}
__device__ __forceinline__ void mma_f16(float* c, const uint32_t* a, const uint32_t* b) {
    asm volatile(
        "mma.sync.aligned.m16n8k16.row.col.f32.f16.f16.f32 "
        "{%0,%1,%2,%3}, {%4,%5,%6,%7}, {%8,%9}, {%0,%1,%2,%3};"
        : "+f"(c[0]), "+f"(c[1]), "+f"(c[2]), "+f"(c[3])
        : "r"(a[0]), "r"(a[1]), "r"(a[2]), "r"(a[3]), "r"(b[0]), "r"(b[1]));
}

// ---------------------------------------------------------------------------
// CTA = 128 t-rows x 128 CO for one (b, f). 8 warps, warp tile 32x64.
// A (x) resident in smem as fp16; B staged per-TAP (32KB), 2 stages.
// Only 5 CTA barriers total.
// ---------------------------------------------------------------------------
__global__ __launch_bounds__(NTHREADS, 2)
void conv_mma_kernel(const float* __restrict__ x,
                     const float* __restrict__ bias,
                     float* __restrict__ y) {
    extern __shared__ char dsm[];
    __shared__ float s_bias[COn];

    const int t0 = blockIdx.x * TILE_M;
    const int f  = blockIdx.y;
    const int b  = blockIdx.z;
    const int tid = threadIdx.x;
    const int wid = tid >> 5;
    const int lane = tid & 31;
    const int wm = (wid >> 1) * 32;      // warp M base (0,32,64,96)
    const int wn = (wid & 1) * 64;       // warp N base (0,64)

    const uint32_t smb = smem_u32(dsm);
    const uint32_t Abase = smb;
    const uint32_t Bbase = smb + A_TOTAL;

    const float* xb = x + ((long long)b * Tn * Fn + f) * CIn;   // + t*4096 + ci
    const __half* wf = g_wBh + (long long)f * Kn * COn * CIn;   // + tap*16384 + o*128 + ci

    if (tid < COn) s_bias[tid] = bias[f * COn + tid];

    // ---- B loader: one full tap -> stage s (8 cp16 per thread) ----
    auto load_B = [&](int tap, int s) {
        const __half* gt = wf + (long long)tap * (COn * CIn);
        const uint32_t Bb = Bbase + s * B_STAGE_BYTES;
        #pragma unroll
        for (int j = 0; j < 8; j++) {
            const int lin  = j * NTHREADS + tid;     // 0..2047
            const int plane = lin >> 9;              // 0..3
            const int rem   = lin & 511;
            const int row   = rem >> 2;              // 0..127
            const int c16   = rem & 3;               // 16B col
            cp16(Bb + plane * B_PLANE_BYTES + SWZ64(row * 64 + c16 * 16),
                 gt + (long long)row * CIn + plane * 32 + c16 * 8);
        }
    };

    // ---- prologue: kick off taps 0 and 1 ----
    load_B(0, 0);
    asm volatile("cp.async.commit_group;");
    load_B(1, 1);
    asm volatile("cp.async.commit_group;");

    // ---- convert A: x rows t0-4 .. t0+127 (132 rows x 128 ci) -> fp16 planes ----
    for (int idx = tid; idx < 132 * 32; idx += NTHREADS) {
        const int row = idx >> 5;
        const int q   = idx & 31;
        const int tg  = t0 - 4 + row;
        float4 v = make_float4(0.f, 0.f, 0.f, 0.f);
        if (tg >= 0)
            v = *reinterpret_cast<const float4*>(xb + (long long)tg * (Fn * CIn) + q * 4);
        __half2 h0 = __floats2half2_rn(v.x, v.y);
        __half2 h1 = __floats2half2_rn(v.z, v.w);
        const int plane = q >> 3;
        const uint32_t off = row * 64 + (q & 7) * 8;
        sts64(Abase + plane * A_PLANE_BYTES + SWZ64(off),
              *reinterpret_cast<uint32_t*>(&h0), *reinterpret_cast<uint32_t*>(&h1));
    }

    // ---- accumulators (init with bias after it is visible) ----
    float acc[2][8][4];

    // ldmatrix lane addressing (16B units within 64B rows)
    const int a_row = wm + (lane & 15);
    const int a_cb  = (lane >> 4) * 16;
    const int b_row = wn + (lane & 7) + ((lane >> 4) << 3);
    const int b_cb  = ((lane >> 3) & 1) * 16;

    bool acc_init = false;

    // ---- main loop over taps ----
    #pragma unroll 1
    for (int tap = 0; tap < Kn; tap++) {
        if (tap < 2) { asm volatile("cp.async.wait_group 1;"); }
        else         { asm volatile("cp.async.wait_group 0;"); }
        __syncthreads();           // B(tap) + (tap==0: A, bias) visible

        if (!acc_init) {
            acc_init = true;
            #pragma unroll
            for (int nf = 0; nf < 8; nf++) {
                const int n = wn + nf * 8 + (lane & 3) * 2;
                const float b0 = s_bias[n], b1 = s_bias[n + 1];
                #pragma unroll
                for (int mf = 0; mf < 2; mf++) {
                    acc[mf][nf][0] = b0; acc[mf][nf][1] = b1;
                    acc[mf][nf][2] = b0; acc[mf][nf][3] = b1;
                }
            }
        }

        const uint32_t Bst = Bbase + (tap & 1) * B_STAGE_BYTES;
        const int arow_sh = 2 * tap;

        #pragma unroll
        for (int plane = 0; plane < 4; plane++) {
            const uint32_t Ab = Abase + plane * A_PLANE_BYTES;
            const uint32_t Bb = Bst + plane * B_PLANE_BYTES;
            #pragma unroll
            for (int ks = 0; ks < 2; ks++) {
                uint32_t afr[2][4], bfr[8][2];
                #pragma unroll
                for (int mf = 0; mf < 2; mf++)
                    ldsm_x4(afr[mf][0], afr[mf][1], afr[mf][2], afr[mf][3],
                            Ab + SWZ64((a_row + mf * 16 + arow_sh) * 64 + ks * 32 + a_cb));
                #pragma unroll
                for (int nf2 = 0; nf2 < 4; nf2++) {
                    uint32_t r0, r1, r2, r3;
                    ldsm_x4(r0, r1, r2, r3,
                            Bb + SWZ64((b_row + nf2 * 16) * 64 + ks * 32 + b_cb));
                    bfr[nf2 * 2][0] = r0;     bfr[nf2 * 2][1] = r1;
                    bfr[nf2 * 2 + 1][0] = r2; bfr[nf2 * 2 + 1][1] = r3;
                }
                #pragma unroll
                for (int mf = 0; mf < 2; mf++)
                    #pragma unroll
                    for (int nf = 0; nf < 8; nf++)
                        mma_f16(acc[mf][nf], afr[mf], bfr[nf]);
            }
        }

        // after tap 0: recycle stage 0 for tap 2 (all warps done with it)
        if (tap == 0) {
            __syncthreads();
            load_B(2, 0);
            asm volatile("cp.async.commit_group;");
        }
    }

    // ---- epilogue ----
    #pragma unroll
    for (int mf = 0; mf < 2; mf++) {
        #pragma unroll
        for (int r2 = 0; r2 < 2; r2++) {
            const int t = t0 + wm + mf * 16 + (lane >> 2) + r2 * 8;
            float* yrow = y + ((long long)(b * Tn + t) * Fn + f) * COn;
            #pragma unroll
            for (int nf = 0; nf < 8; nf++) {
                const int n = wn + nf * 8 + (lane & 3) * 2;
                float2 v = make_float2(acc[mf][nf][r2 * 2], acc[mf][nf][r2 * 2 + 1]);
                *reinterpret_cast<float2*>(yrow + n) = v;
            }
        }
    }
}

// ---------------------------------------------------------------------------
extern "C" void kernel_launch(void* const* d_in, const int* in_sizes, int n_in,
                              void* d_out, int out_size) {
    const float* x    = (const float*)d_in[0];  // [B, T, F, CI]
    const float* w    = (const float*)d_in[1];  // [F, CO, CI, K]
    const float* bias = (const float*)d_in[2];  // [F, CO]
    float* y = (float*)d_out;                   // [B, T, F, CO]
    (void)in_sizes; (void)n_in; (void)out_size;

    {
        const int total = Fn * Kn * COn * CIn;
        prep_w<<<(total + 255) / 256, 256>>>(w);
    }
    {
        static bool attr_set = false;
        if (!attr_set) {
            cudaFuncSetAttribute(conv_mma_kernel,
                                 cudaFuncAttributeMaxDynamicSharedMemorySize, DYN_SMEM);
            attr_set = true;
        }
        dim3 grid(Tn / TILE_M, Fn, Bn);   // (4, 32, 16) = 2048 CTAs
        conv_mma_kernel<<<grid, NTHREADS, DYN_SMEM>>>(x, bias, y);
    }
}

// round 8
// speedup vs baseline: 1.1639x; 1.0819x over previous
#include <cuda_runtime.h>
#include <cuda_fp16.h>
#include <cstdint>

// Problem constants
#define Bn   16
#define Tn   512
#define Fn   32
#define CIn  128
#define COn  128
#define Kn   3
#define DILn 2

#define NTHREADS 256           // 8 warps: 2(M) x 4(N), warp tile 64x32

// B resident: 3 taps x 4 ci-planes x 128 rows x 64B = 96KB
#define B_PLANE_BYTES 8192
#define B_TAP_BYTES   (4 * B_PLANE_BYTES)     // 32768
#define B_TOTAL       (3 * B_TAP_BYTES)       // 98304
// A buffer: 4 ci-planes x 136 rows x 64B (132 used: 128 + 4 halo)
#define A_PLANE_BYTES (136 * 64)              // 8704
#define A_BUF_BYTES   (4 * A_PLANE_BYTES)     // 34816
#define DYN_SMEM (B_TOTAL + 2 * A_BUF_BYTES)  // 167936

#define SWZ64(off) ((off) ^ (((off) >> 3) & 0x30))

// Weights as fp16: wBh[f][tap][o][ci]
__device__ __half g_wBh[Fn * Kn * COn * CIn];

// ---------------------------------------------------------------------------
__global__ void prep_w(const float* __restrict__ w) {
    int idx = blockIdx.x * blockDim.x + threadIdx.x;
    const int total = Fn * Kn * COn * CIn;
    if (idx >= total) return;
    int i = idx % CIn;
    int o = (idx / CIn) % COn;
    int k = (idx / (CIn * COn)) % Kn;
    int f = idx / (CIn * COn * Kn);
    g_wBh[idx] = __float2half_rn(w[((f * COn + o) * CIn + i) * Kn + k]);
}

// ---------------------------------------------------------------------------
__device__ __forceinline__ uint32_t smem_u32(const void* p) {
    uint32_t a;
    asm("{ .reg .u64 t; cvta.to.shared.u64 t, %1; cvt.u32.u64 %0, t; }" : "=r"(a) : "l"(p));
    return a;
}
__device__ __forceinline__ void cp16(uint32_t saddr, const void* gaddr) {
    asm volatile("cp.async.cg.shared.global [%0], [%1], 16;"
                 :: "r"(saddr), "l"(gaddr));
}
__device__ __forceinline__ void sts64(uint32_t saddr, uint32_t v0, uint32_t v1) {
    asm volatile("st.shared.v2.b32 [%0], {%1, %2};" :: "r"(saddr), "r"(v0), "r"(v1));
}
__device__ __forceinline__ void ldsm_x4(uint32_t& r0, uint32_t& r1, uint32_t& r2, uint32_t& r3,
                                        uint32_t addr) {
    asm volatile("ldmatrix.sync.aligned.m8n8.x4.shared.b16 {%0,%1,%2,%3}, [%4];"
                 : "=r"(r0), "=r"(r1), "=r"(r2), "=r"(r3) : "r"(addr));
}
__device__ __forceinline__ void mma_f16(float* c, const uint32_t* a, const uint32_t* b) {
    asm volatile(
        "mma.sync.aligned.m16n8k16.row.col.f32.f16.f16.f32 "
        "{%0,%1,%2,%3}, {%4,%5,%6,%7}, {%8,%9}, {%0,%1,%2,%3};"
        : "+f"(c[0]), "+f"(c[1]), "+f"(c[2]), "+f"(c[3])
        : "r"(a[0]), "r"(a[1]), "r"(a[2]), "r"(a[3]), "r"(b[0]), "r"(b[1]));
}

// ---------------------------------------------------------------------------
// CTA = 256 t-rows x 128 CO for one (b, f, half). 8 warps, warp tile 64x32.
// B: all 3 taps resident (96KB, loaded once). A: fp16 double buffer.
// 2 CTA barriers total.
// ---------------------------------------------------------------------------
__global__ __launch_bounds__(NTHREADS, 1)
void conv_mma_kernel(const float* __restrict__ x,
                     const float* __restrict__ bias,
                     float* __restrict__ y) {
    extern __shared__ char dsm[];

    const int th = blockIdx.x;           // half index (0,1)
    const int f  = blockIdx.y;
    const int b  = blockIdx.z;
    const int t0 = th * 256;
    const int tid = threadIdx.x;
    const int wid = tid >> 5;
    const int lane = tid & 31;
    const int wm = (wid & 1) * 64;       // warp M base (0,64)
    const int wn = (wid >> 1) * 32;      // warp N base (0,32,64,96)

    const uint32_t smb = smem_u32(dsm);
    const uint32_t Bbase  = smb;
    const uint32_t Abase0 = smb + B_TOTAL;
    const uint32_t Abase1 = Abase0 + A_BUF_BYTES;

    const float* xb = x + ((long long)b * Tn * Fn + f) * CIn;   // + t*4096 + ci
    const __half* wf = g_wBh + (long long)f * Kn * COn * CIn;

    // ---- bias in registers (4 nf x 2) ----
    float bias_r[8];
    #pragma unroll
    for (int nf = 0; nf < 4; nf++) {
        const int n = wn + nf * 8 + (lane & 3) * 2;
        bias_r[nf * 2]     = __ldg(bias + f * COn + n);
        bias_r[nf * 2 + 1] = __ldg(bias + f * COn + n + 1);
    }

    // ---- load ALL B (3 taps) via cp.async ----
    {
        #pragma unroll
        for (int j = 0; j < 24; j++) {
            const int lin   = j * NTHREADS + tid;    // 0..6143
            const int tap   = lin / 2048;
            const int rem1  = lin % 2048;
            const int plane = rem1 >> 9;             // 0..3
            const int rem   = rem1 & 511;
            const int row   = rem >> 2;              // 0..127
            const int c16   = rem & 3;
            cp16(Bbase + tap * B_TAP_BYTES + plane * B_PLANE_BYTES
                       + SWZ64(row * 64 + c16 * 16),
                 wf + (long long)tap * (COn * CIn) + (long long)row * CIn
                    + plane * 32 + c16 * 8);
        }
        asm volatile("cp.async.commit_group;");
    }

    // ---- A converter: rows tstart-4 .. tstart+127 -> fp16 planes ----
    auto convertA = [&](int tstart, uint32_t Abuf) {
        #pragma unroll 4
        for (int idx = tid; idx < 132 * 32; idx += NTHREADS) {
            const int row = idx >> 5;
            const int q   = idx & 31;
            const int tg  = tstart - 4 + row;
            float4 v = make_float4(0.f, 0.f, 0.f, 0.f);
            if (tg >= 0)
                v = *reinterpret_cast<const float4*>(xb + (long long)tg * (Fn * CIn) + q * 4);
            __half2 h0 = __floats2half2_rn(v.x, v.y);
            __half2 h1 = __floats2half2_rn(v.z, v.w);
            sts64(Abuf + (q >> 3) * A_PLANE_BYTES + SWZ64(row * 64 + (q & 7) * 8),
                  *reinterpret_cast<uint32_t*>(&h0), *reinterpret_cast<uint32_t*>(&h1));
        }
    };

    convertA(t0, Abase0);

    asm volatile("cp.async.wait_group 0;");
    __syncthreads();                     // B + A(tile0) ready

    // ldmatrix lane addressing (16B units within 64B rows)
    const int a_row = wm + (lane & 15);
    const int a_cb  = (lane >> 4) * 16;
    const int b_row = wn + (lane & 7) + ((lane >> 4) << 3);
    const int b_cb  = ((lane >> 3) & 1) * 16;

    float acc[4][4][4];                  // [mf 16-row][nf 8-col][elem]

    auto init_acc = [&]() {
        #pragma unroll
        for (int mf = 0; mf < 4; mf++)
            #pragma unroll
            for (int nf = 0; nf < 4; nf++) {
                acc[mf][nf][0] = bias_r[nf * 2];
                acc[mf][nf][1] = bias_r[nf * 2 + 1];
                acc[mf][nf][2] = bias_r[nf * 2];
                acc[mf][nf][3] = bias_r[nf * 2 + 1];
            }
    };

    auto compute_tap = [&](int tap, uint32_t Abuf) {
        const uint32_t Bt = Bbase + tap * B_TAP_BYTES;
        const int arow_sh = 2 * tap;
        #pragma unroll
        for (int plane = 0; plane < 4; plane++) {
            const uint32_t Ab = Abuf + plane * A_PLANE_BYTES;
            const uint32_t Bb = Bt + plane * B_PLANE_BYTES;
            #pragma unroll
            for (int ks = 0; ks < 2; ks++) {
                uint32_t afr[4][4], bfr[4][2];
                #pragma unroll
                for (int mf = 0; mf < 4; mf++)
                    ldsm_x4(afr[mf][0], afr[mf][1], afr[mf][2], afr[mf][3],
                            Ab + SWZ64((a_row + mf * 16 + arow_sh) * 64 + ks * 32 + a_cb));
                #pragma unroll
                for (int nf2 = 0; nf2 < 2; nf2++) {
                    uint32_t r0, r1, r2, r3;
                    ldsm_x4(r0, r1, r2, r3,
                            Bb + SWZ64((b_row + nf2 * 16) * 64 + ks * 32 + b_cb));
                    bfr[nf2 * 2][0] = r0;     bfr[nf2 * 2][1] = r1;
                    bfr[nf2 * 2 + 1][0] = r2; bfr[nf2 * 2 + 1][1] = r3;
                }
                #pragma unroll
                for (int mf = 0; mf < 4; mf++)
                    #pragma unroll
                    for (int nf = 0; nf < 4; nf++)
                        mma_f16(acc[mf][nf], afr[mf], bfr[nf]);
            }
        }
    };

    auto store_y = [&](int tstart) {
        #pragma unroll
        for (int mf = 0; mf < 4; mf++) {
            #pragma unroll
            for (int r2 = 0; r2 < 2; r2++) {
                const int t = tstart + wm + mf * 16 + (lane >> 2) + r2 * 8;
                float* yrow = y + ((long long)(b * Tn + t) * Fn + f) * COn;
                #pragma unroll
                for (int nf = 0; nf < 4; nf++) {
                    const int n = wn + nf * 8 + (lane & 3) * 2;
                    *reinterpret_cast<float2*>(yrow + n) =
                        make_float2(acc[mf][nf][r2 * 2], acc[mf][nf][r2 * 2 + 1]);
                }
            }
        }
    };

    // ======== tile 0 ========
    init_acc();
    compute_tap(0, Abase0);
    convertA(t0 + 128, Abase1);          // overlap A(tile1) with taps 1,2
    compute_tap(1, Abase0);
    compute_tap(2, Abase0);
    store_y(t0);

    __syncthreads();                     // A(tile1) visible to all warps

    // ======== tile 1 ========
    init_acc();
    compute_tap(0, Abase1);
    compute_tap(1, Abase1);
    compute_tap(2, Abase1);
    store_y(t0 + 128);
}

// ---------------------------------------------------------------------------
extern "C" void kernel_launch(void* const* d_in, const int* in_sizes, int n_in,
                              void* d_out, int out_size) {
    const float* x    = (const float*)d_in[0];  // [B, T, F, CI]
    const float* w    = (const float*)d_in[1];  // [F, CO, CI, K]
    const float* bias = (const float*)d_in[2];  // [F, CO]
    float* y = (float*)d_out;                   // [B, T, F, CO]
    (void)in_sizes; (void)n_in; (void)out_size;

    {
        const int total = Fn * Kn * COn * CIn;
        prep_w<<<(total + 255) / 256, 256>>>(w);
    }
    {
        static bool attr_set = false;
        if (!attr_set) {
            cudaFuncSetAttribute(conv_mma_kernel,
                                 cudaFuncAttributeMaxDynamicSharedMemorySize, DYN_SMEM);
            attr_set = true;
        }
        dim3 grid(2, Fn, Bn);   // 1024 CTAs: (half, f, b)
        conv_mma_kernel<<<grid, NTHREADS, DYN_SMEM>>>(x, bias, y);
    }
}

// round 9
// speedup vs baseline: 1.3339x; 1.1461x over previous
#include <cuda_runtime.h>
#include <cuda_fp16.h>
#include <cstdint>

// Problem constants
#define Bn   16
#define Tn   512
#define Fn   32
#define CIn  128
#define COn  128
#define Kn   3
#define DILn 2

#define NTHREADS 512           // 16 warps: 4(M) x 4(N), warp tile 64x32

// B resident: 3 taps x 4 ci-planes x 128 rows x 64B = 96KB
#define B_PLANE_BYTES 8192
#define B_TAP_BYTES   (4 * B_PLANE_BYTES)     // 32768
#define B_TOTAL       (3 * B_TAP_BYTES)       // 98304
// A buffer: 4 ci-planes x 264 rows x 64B (260 used: 256 + 4 halo)
#define A_ROWS        264
#define A_PLANE_BYTES (A_ROWS * 64)           // 16896
#define A_TOTAL       (4 * A_PLANE_BYTES)     // 67584
#define DYN_SMEM (B_TOTAL + A_TOTAL)          // 165888 (162KB)

#define SWZ64(off) ((off) ^ (((off) >> 3) & 0x30))

// Weights as fp16: wBh[f][tap][o][ci]
__device__ __half g_wBh[Fn * Kn * COn * CIn];

// ---------------------------------------------------------------------------
__global__ void prep_w(const float* __restrict__ w) {
    int idx = blockIdx.x * blockDim.x + threadIdx.x;
    const int total = Fn * Kn * COn * CIn;
    if (idx >= total) return;
    int i = idx % CIn;
    int o = (idx / CIn) % COn;
    int k = (idx / (CIn * COn)) % Kn;
    int f = idx / (CIn * COn * Kn);
    g_wBh[idx] = __float2half_rn(w[((f * COn + o) * CIn + i) * Kn + k]);
}

// ---------------------------------------------------------------------------
__device__ __forceinline__ uint32_t smem_u32(const void* p) {
    uint32_t a;
    asm("{ .reg .u64 t; cvta.to.shared.u64 t, %1; cvt.u32.u64 %0, t; }" : "=r"(a) : "l"(p));
    return a;
}
__device__ __forceinline__ void cp16(uint32_t saddr, const void* gaddr) {
    asm volatile("cp.async.cg.shared.global [%0], [%1], 16;"
                 :: "r"(saddr), "l"(gaddr));
}
__device__ __forceinline__ void sts64(uint32_t saddr, uint32_t v0, uint32_t v1) {
    asm volatile("st.shared.v2.b32 [%0], {%1, %2};" :: "r"(saddr), "r"(v0), "r"(v1));
}
__device__ __forceinline__ void ldsm_x4(uint32_t& r0, uint32_t& r1, uint32_t& r2, uint32_t& r3,
                                        uint32_t addr) {
    asm volatile("ldmatrix.sync.aligned.m8n8.x4.shared.b16 {%0,%1,%2,%3}, [%4];"
                 : "=r"(r0), "=r"(r1), "=r"(r2), "=r"(r3) : "r"(addr));
}
__device__ __forceinline__ void mma_f16(float* c, const uint32_t* a, const uint32_t* b) {
    asm volatile(
        "mma.sync.aligned.m16n8k16.row.col.f32.f16.f16.f32 "
        "{%0,%1,%2,%3}, {%4,%5,%6,%7}, {%8,%9}, {%0,%1,%2,%3};"
        : "+f"(c[0]), "+f"(c[1]), "+f"(c[2]), "+f"(c[3])
        : "r"(a[0]), "r"(a[1]), "r"(a[2]), "r"(a[3]), "r"(b[0]), "r"(b[1]));
}

// ---------------------------------------------------------------------------
// CTA = 256 t-rows x 128 CO for one (b, f, half). 16 warps, warp tile 64x32.
// B: all 3 taps resident (96KB). A: one resident fp16 buffer (260 rows).
// ONE CTA barrier total; taps run back-to-back.
// ---------------------------------------------------------------------------
__global__ __launch_bounds__(NTHREADS, 1)
void conv_mma_kernel(const float* __restrict__ x,
                     const float* __restrict__ bias,
                     float* __restrict__ y) {
    extern __shared__ char dsm[];

    const int t0 = blockIdx.x * 256;     // half index (0,1) * 256
    const int f  = blockIdx.y;
    const int b  = blockIdx.z;
    const int tid = threadIdx.x;
    const int wid = tid >> 5;
    const int lane = tid & 31;
    const int wm = (wid & 3) * 64;       // warp M base (0,64,128,192)
    const int wn = (wid >> 2) * 32;      // warp N base (0,32,64,96)

    const uint32_t smb = smem_u32(dsm);
    const uint32_t Bbase = smb;
    const uint32_t Abase = smb + B_TOTAL;

    const float* xb = x + ((long long)b * Tn * Fn + f) * CIn;   // + t*4096 + ci
    const __half* wf = g_wBh + (long long)f * Kn * COn * CIn;

    // ---- bias in registers (4 nf x 2) ----
    float bias_r[8];
    #pragma unroll
    for (int nf = 0; nf < 4; nf++) {
        const int n = wn + nf * 8 + (lane & 3) * 2;
        bias_r[nf * 2]     = __ldg(bias + f * COn + n);
        bias_r[nf * 2 + 1] = __ldg(bias + f * COn + n + 1);
    }

    // ---- load ALL B (3 taps = 6144 float4s, 12 per thread) via cp.async ----
    {
        #pragma unroll
        for (int j = 0; j < 12; j++) {
            const int lin   = j * NTHREADS + tid;    // 0..6143
            const int tap   = lin / 2048;
            const int rem1  = lin % 2048;
            const int plane = rem1 >> 9;             // 0..3
            const int rem   = rem1 & 511;
            const int row   = rem >> 2;              // 0..127
            const int c16   = rem & 3;
            cp16(Bbase + tap * B_TAP_BYTES + plane * B_PLANE_BYTES
                       + SWZ64(row * 64 + c16 * 16),
                 wf + (long long)tap * (COn * CIn) + (long long)row * CIn
                    + plane * 32 + c16 * 8);
        }
        asm volatile("cp.async.commit_group;");
    }

    // ---- convert A: rows t0-4 .. t0+255 (260 rows x 128 ci) -> fp16 planes ----
    {
        #pragma unroll 4
        for (int idx = tid; idx < 260 * 32; idx += NTHREADS) {
            const int row = idx >> 5;
            const int q   = idx & 31;
            const int tg  = t0 - 4 + row;
            float4 v = make_float4(0.f, 0.f, 0.f, 0.f);
            if (tg >= 0)
                v = *reinterpret_cast<const float4*>(xb + (long long)tg * (Fn * CIn) + q * 4);
            __half2 h0 = __floats2half2_rn(v.x, v.y);
            __half2 h1 = __floats2half2_rn(v.z, v.w);
            sts64(Abase + (q >> 3) * A_PLANE_BYTES + SWZ64(row * 64 + (q & 7) * 8),
                  *reinterpret_cast<uint32_t*>(&h0), *reinterpret_cast<uint32_t*>(&h1));
        }
    }

    asm volatile("cp.async.wait_group 0;");
    __syncthreads();                     // B + A ready (the only barrier)

    // ldmatrix lane addressing (16B units within 64B rows)
    const int a_row = wm + (lane & 15);
    const int a_cb  = (lane >> 4) * 16;
    const int b_row = wn + (lane & 7) + ((lane >> 4) << 3);
    const int b_cb  = ((lane >> 3) & 1) * 16;

    // ---- accumulators (init with bias) ----
    float acc[4][4][4];                  // [mf 16-row][nf 8-col][elem]
    #pragma unroll
    for (int mf = 0; mf < 4; mf++)
        #pragma unroll
        for (int nf = 0; nf < 4; nf++) {
            acc[mf][nf][0] = bias_r[nf * 2];
            acc[mf][nf][1] = bias_r[nf * 2 + 1];
            acc[mf][nf][2] = bias_r[nf * 2];
            acc[mf][nf][3] = bias_r[nf * 2 + 1];
        }

    // ---- compute: 3 taps back-to-back, no syncs ----
    #pragma unroll
    for (int tap = 0; tap < Kn; tap++) {
        const uint32_t Bt = Bbase + tap * B_TAP_BYTES;
        const int arow_sh = 2 * tap;     // tap time-shift in resident rows
        #pragma unroll
        for (int plane = 0; plane < 4; plane++) {
            const uint32_t Ab = Abase + plane * A_PLANE_BYTES;
            const uint32_t Bb = Bt + plane * B_PLANE_BYTES;
            #pragma unroll
            for (int ks = 0; ks < 2; ks++) {
                uint32_t afr[4][4], bfr[4][2];
                #pragma unroll
                for (int mf = 0; mf < 4; mf++)
                    ldsm_x4(afr[mf][0], afr[mf][1], afr[mf][2], afr[mf][3],
                            Ab + SWZ64((a_row + mf * 16 + arow_sh) * 64 + ks * 32 + a_cb));
                #pragma unroll
                for (int nf2 = 0; nf2 < 2; nf2++) {
                    uint32_t r0, r1, r2, r3;
                    ldsm_x4(r0, r1, r2, r3,
                            Bb + SWZ64((b_row + nf2 * 16) * 64 + ks * 32 + b_cb));
                    bfr[nf2 * 2][0] = r0;     bfr[nf2 * 2][1] = r1;
                    bfr[nf2 * 2 + 1][0] = r2; bfr[nf2 * 2 + 1][1] = r3;
                }
                #pragma unroll
                for (int mf = 0; mf < 4; mf++)
                    #pragma unroll
                    for (int nf = 0; nf < 4; nf++)
                        mma_f16(acc[mf][nf], afr[mf], bfr[nf]);
            }
        }
    }

    // ---- store ----
    #pragma unroll
    for (int mf = 0; mf < 4; mf++) {
        #pragma unroll
        for (int r2 = 0; r2 < 2; r2++) {
            const int t = t0 + wm + mf * 16 + (lane >> 2) + r2 * 8;
            float* yrow = y + ((long long)(b * Tn + t) * Fn + f) * COn;
            #pragma unroll
            for (int nf = 0; nf < 4; nf++) {
                const int n = wn + nf * 8 + (lane & 3) * 2;
                *reinterpret_cast<float2*>(yrow + n) =
                    make_float2(acc[mf][nf][r2 * 2], acc[mf][nf][r2 * 2 + 1]);
            }
        }
    }
}

// ---------------------------------------------------------------------------
extern "C" void kernel_launch(void* const* d_in, const int* in_sizes, int n_in,
                              void* d_out, int out_size) {
    const float* x    = (const float*)d_in[0];  // [B, T, F, CI]
    const float* w    = (const float*)d_in[1];  // [F, CO, CI, K]
    const float* bias = (const float*)d_in[2];  // [F, CO]
    float* y = (float*)d_out;                   // [B, T, F, CO]
    (void)in_sizes; (void)n_in; (void)out_size;

    {
        const int total = Fn * Kn * COn * CIn;
        prep_w<<<(total + 255) / 256, 256>>>(w);
    }
    {
        static bool attr_set = false;
        if (!attr_set) {
            cudaFuncSetAttribute(conv_mma_kernel,
                                 cudaFuncAttributeMaxDynamicSharedMemorySize, DYN_SMEM);
            attr_set = true;
        }
        dim3 grid(2, Fn, Bn);   // 1024 CTAs: (half, f, b)
        conv_mma_kernel<<<grid, NTHREADS, DYN_SMEM>>>(x, bias, y);
    }
}

// round 10
// speedup vs baseline: 1.4693x; 1.1015x over previous
#include <cuda_runtime.h>
#include <cuda_fp16.h>
#include <cstdint>

// Problem constants
#define Bn   16
#define Tn   512
#define Fn   32
#define CIn  128
#define COn  128
#define Kn   3
#define DILn 2

#define NTHREADS 512           // 16 warps: 4(M) x 4(N), warp tile 32x32
#define GRIDX    148           // persistent CTAs (one wave)
#define NTILES   2048          // 32 f * 16 b * 4 t-segments (M=128)

// B resident: 3 taps x 4 ci-planes x 128 rows x 64B = 96KB
#define B_PLANE_BYTES 8192
#define B_TAP_BYTES   (4 * B_PLANE_BYTES)     // 32768
#define B_TOTAL       (3 * B_TAP_BYTES)       // 98304
// A buffer: 4 ci-planes x 136 rows x 64B (132 used: 128 + 4 halo)
#define A_PLANE_BYTES (136 * 64)              // 8704 (512-aligned)
#define A_TOTAL       (4 * A_PLANE_BYTES)     // 34816
#define DYN_SMEM (B_TOTAL + A_TOTAL)          // 133120 (130KB)

#define A_F4   (132 * 32)      // float4s per A tile = 4224
#define SWZ64(off) ((off) ^ (((off) >> 3) & 0x30))

// Weights as fp16: wBh[f][tap][o][ci]
__device__ __half g_wBh[Fn * Kn * COn * CIn];

// ---------------------------------------------------------------------------
__global__ void prep_w(const float* __restrict__ w) {
    int idx = blockIdx.x * blockDim.x + threadIdx.x;
    const int total = Fn * Kn * COn * CIn;
    if (idx >= total) return;
    int i = idx % CIn;
    int o = (idx / CIn) % COn;
    int k = (idx / (CIn * COn)) % Kn;
    int f = idx / (CIn * COn * Kn);
    g_wBh[idx] = __float2half_rn(w[((f * COn + o) * CIn + i) * Kn + k]);
}

// ---------------------------------------------------------------------------
__device__ __forceinline__ uint32_t smem_u32(const void* p) {
    uint32_t a;
    asm("{ .reg .u64 t; cvta.to.shared.u64 t, %1; cvt.u32.u64 %0, t; }" : "=r"(a) : "l"(p));
    return a;
}
__device__ __forceinline__ void cp16(uint32_t saddr, const void* gaddr) {
    asm volatile("cp.async.cg.shared.global [%0], [%1], 16;"
                 :: "r"(saddr), "l"(gaddr));
}
__device__ __forceinline__ void sts64(uint32_t saddr, uint32_t v0, uint32_t v1) {
    asm volatile("st.shared.v2.b32 [%0], {%1, %2};" :: "r"(saddr), "r"(v0), "r"(v1));
}
__device__ __forceinline__ void ldsm_x4(uint32_t& r0, uint32_t& r1, uint32_t& r2, uint32_t& r3,
                                        uint32_t addr) {
    asm volatile("ldmatrix.sync.aligned.m8n8.x4.shared.b16 {%0,%1,%2,%3}, [%4];"
                 : "=r"(r0), "=r"(r1), "=r"(r2), "=r"(r3) : "r"(addr));
}
__device__ __forceinline__ void mma_f16(float* c, const uint32_t* a, const uint32_t* b) {
    asm volatile(
        "mma.sync.aligned.m16n8k16.row.col.f32.f16.f16.f32 "
        "{%0,%1,%2,%3}, {%4,%5,%6,%7}, {%8,%9}, {%0,%1,%2,%3};"
        : "+f"(c[0]), "+f"(c[1]), "+f"(c[2]), "+f"(c[3])
        : "r"(a[0]), "r"(a[1]), "r"(a[2]), "r"(a[3]), "r"(b[0]), "r"(b[1]));
}

// ---------------------------------------------------------------------------
// Persistent kernel. Tile = 128 t-rows x 128 CO. Tiles ordered by f so B
// reloads happen at most once per CTA. A single-buffered; next tile's A is
// prefetched into registers during the current tile's compute.
// ---------------------------------------------------------------------------
__global__ __launch_bounds__(NTHREADS, 1)
void conv_mma_kernel(const float* __restrict__ x,
                     const float* __restrict__ bias,
                     float* __restrict__ y) {
    extern __shared__ char dsm[];

    const int k = blockIdx.x;
    const int tid = threadIdx.x;
    const int wid = tid >> 5;
    const int lane = tid & 31;
    const int wm = (wid & 3) * 32;       // warp M base (0,32,64,96)
    const int wn = (wid >> 2) * 32;      // warp N base (0,32,64,96)

    const int start = (k * NTILES) / GRIDX;
    const int end   = ((k + 1) * NTILES) / GRIDX;

    const uint32_t smb = smem_u32(dsm);
    const uint32_t Bbase = smb;
    const uint32_t Abase = smb + B_TOTAL;

    // ---- B loader (one f): 6144 float4s, 12 per thread ----
    auto issue_B = [&](int f_) {
        const __half* wf = g_wBh + (long long)f_ * Kn * COn * CIn;
        #pragma unroll
        for (int j = 0; j < 12; j++) {
            const int lin   = j * NTHREADS + tid;
            const int tap   = lin / 2048;
            const int rem1  = lin % 2048;
            const int plane = rem1 >> 9;
            const int rem   = rem1 & 511;
            const int row   = rem >> 2;
            const int c16   = rem & 3;
            cp16(Bbase + tap * B_TAP_BYTES + plane * B_PLANE_BYTES
                       + SWZ64(row * 64 + c16 * 16),
                 wf + (long long)tap * (COn * CIn) + (long long)row * CIn
                    + plane * 32 + c16 * 8);
        }
        asm volatile("cp.async.commit_group;");
    };

    // ---- A prefetch (global -> regs) and commit (regs -> smem fp16) ----
    auto ldgA = [&](int f_, int b_, int t0_, float4* v) {
        const float* xb = x + ((long long)b_ * Tn * Fn + f_) * CIn;
        #pragma unroll
        for (int i = 0; i < 9; i++) {
            const int idx2 = tid + i * NTHREADS;
            const int row = idx2 >> 5;
            const int q   = idx2 & 31;
            const int tg  = t0_ - 4 + row;
            v[i] = make_float4(0.f, 0.f, 0.f, 0.f);
            if (idx2 < A_F4 && tg >= 0)
                v[i] = *reinterpret_cast<const float4*>(
                    xb + (long long)tg * (Fn * CIn) + q * 4);
        }
    };
    auto stsA = [&](const float4* v) {
        #pragma unroll
        for (int i = 0; i < 9; i++) {
            const int idx2 = tid + i * NTHREADS;
            if (idx2 < A_F4) {
                const int row = idx2 >> 5;
                const int q   = idx2 & 31;
                __half2 h0 = __floats2half2_rn(v[i].x, v[i].y);
                __half2 h1 = __floats2half2_rn(v[i].z, v[i].w);
                sts64(Abase + (q >> 3) * A_PLANE_BYTES + SWZ64(row * 64 + (q & 7) * 8),
                      *reinterpret_cast<const uint32_t*>(&h0),
                      *reinterpret_cast<const uint32_t*>(&h1));
            }
        }
    };

    // tile decode: idx = f*64 + b*4 + seg
    auto dec_f  = [](int idx) { return idx >> 6; };
    auto dec_b  = [](int idx) { return (idx >> 2) & 15; };
    auto dec_t0 = [](int idx) { return (idx & 3) * 128; };

    // ---- prologue ----
    int curf = dec_f(start);
    issue_B(curf);
    {
        float4 v0[9];
        ldgA(curf, dec_b(start), dec_t0(start), v0);
        stsA(v0);
    }
    asm volatile("cp.async.wait_group 0;");
    __syncthreads();

    // ldmatrix lane addressing
    const int a_row = wm + (lane & 15);
    const int a_cb  = (lane >> 4) * 16;
    const int b_row = wn + (lane & 7) + ((lane >> 4) << 3);
    const int b_cb  = ((lane >> 3) & 1) * 16;

    // ---- persistent tile loop ----
    for (int idx = start; idx < end; idx++) {
        const int f  = dec_f(idx);
        const int b  = dec_b(idx);
        const int t0 = dec_t0(idx);
        const bool have_next = (idx + 1 < end);
        int nf = 0, nb = 0, nt0 = 0;

        // prefetch next A into registers (latency hides under compute)
        float4 v[9];
        if (have_next) {
            nf = dec_f(idx + 1); nb = dec_b(idx + 1); nt0 = dec_t0(idx + 1);
            ldgA(nf, nb, nt0, v);
        }

        // bias for this f
        float bias_r[8];
        #pragma unroll
        for (int nfo = 0; nfo < 4; nfo++) {
            const int n = wn + nfo * 8 + (lane & 3) * 2;
            bias_r[nfo * 2]     = __ldg(bias + f * COn + n);
            bias_r[nfo * 2 + 1] = __ldg(bias + f * COn + n + 1);
        }

        // accumulators
        float acc[2][4][4];
        #pragma unroll
        for (int mf = 0; mf < 2; mf++)
            #pragma unroll
            for (int nfo = 0; nfo < 4; nfo++) {
                acc[mf][nfo][0] = bias_r[nfo * 2];
                acc[mf][nfo][1] = bias_r[nfo * 2 + 1];
                acc[mf][nfo][2] = bias_r[nfo * 2];
                acc[mf][nfo][3] = bias_r[nfo * 2 + 1];
            }

        // compute: 3 taps x 4 planes x 2 ksteps
        #pragma unroll
        for (int tap = 0; tap < Kn; tap++) {
            const uint32_t Bt = Bbase + tap * B_TAP_BYTES;
            const int arow_sh = 2 * tap;
            #pragma unroll
            for (int plane = 0; plane < 4; plane++) {
                const uint32_t Ab = Abase + plane * A_PLANE_BYTES;
                const uint32_t Bb = Bt + plane * B_PLANE_BYTES;
                #pragma unroll
                for (int ks = 0; ks < 2; ks++) {
                    uint32_t afr[2][4], bfr[4][2];
                    #pragma unroll
                    for (int mf = 0; mf < 2; mf++)
                        ldsm_x4(afr[mf][0], afr[mf][1], afr[mf][2], afr[mf][3],
                                Ab + SWZ64((a_row + mf * 16 + arow_sh) * 64
                                           + ks * 32 + a_cb));
                    #pragma unroll
                    for (int nf2 = 0; nf2 < 2; nf2++) {
                        uint32_t r0, r1, r2, r3;
                        ldsm_x4(r0, r1, r2, r3,
                                Bb + SWZ64((b_row + nf2 * 16) * 64 + ks * 32 + b_cb));
                        bfr[nf2 * 2][0] = r0;     bfr[nf2 * 2][1] = r1;
                        bfr[nf2 * 2 + 1][0] = r2; bfr[nf2 * 2 + 1][1] = r3;
                    }
                    #pragma unroll
                    for (int mf = 0; mf < 2; mf++)
                        #pragma unroll
                        for (int nfo = 0; nfo < 4; nfo++)
                            mma_f16(acc[mf][nfo], afr[mf], bfr[nfo]);
                }
            }
        }

        // store y
        #pragma unroll
        for (int mf = 0; mf < 2; mf++) {
            #pragma unroll
            for (int r2 = 0; r2 < 2; r2++) {
                const int t = t0 + wm + mf * 16 + (lane >> 2) + r2 * 8;
                float* yrow = y + ((long long)(b * Tn + t) * Fn + f) * COn;
                #pragma unroll
                for (int nfo = 0; nfo < 4; nfo++) {
                    const int n = wn + nfo * 8 + (lane & 3) * 2;
                    *reinterpret_cast<float2*>(yrow + n) =
                        make_float2(acc[mf][nfo][r2 * 2], acc[mf][nfo][r2 * 2 + 1]);
                }
            }
        }

        __syncthreads();                 // all warps done reading A (and B if reload)

        if (have_next) {
            stsA(v);                     // commit next A to smem
            if (nf != curf) {            // crossed an f boundary: reload B
                issue_B(nf);
                curf = nf;
            }
            asm volatile("cp.async.wait_group 0;");
            __syncthreads();             // next A (+B) visible
        }
    }
}

// ---------------------------------------------------------------------------
extern "C" void kernel_launch(void* const* d_in, const int* in_sizes, int n_in,
                              void* d_out, int out_size) {
    const float* x    = (const float*)d_in[0];  // [B, T, F, CI]
    const float* w    = (const float*)d_in[1];  // [F, CO, CI, K]
    const float* bias = (const float*)d_in[2];  // [F, CO]
    float* y = (float*)d_out;                   // [B, T, F, CO]
    (void)in_sizes; (void)n_in; (void)out_size;

    {
        const int total = Fn * Kn * COn * CIn;
        prep_w<<<(total + 255) / 256, 256>>>(w);
    }
    {
        static bool attr_set = false;
        if (!attr_set) {
            cudaFuncSetAttribute(conv_mma_kernel,
                                 cudaFuncAttributeMaxDynamicSharedMemorySize, DYN_SMEM);
            attr_set = true;
        }
        conv_mma_kernel<<<GRIDX, NTHREADS, DYN_SMEM>>>(x, bias, y);
    }
}